// round 12
// baseline (speedup 1.0000x reference)
#include <cuda_runtime.h>
#include <cuda_fp16.h>
#include <cstdint>

#define NUM_E 16
#define D_IN  2048
#define D_OUT 8192
#define T_TOK 8192

// CTA 128(M) x 128(N), BK=64 (4 k16 steps/chunk). 8 warps = 2(M) x 4(N),
// warp tile 64x32. fp16 2-term (A rn via pre-pass, B hi+lo split in-kernel).
#define BM 128
#define BN 128
#define BK 64
#define NCHUNK (D_IN / BK)   // 32
#define THREADS 256

#define REG_SZ  4096
#define A_T     0                     // 16KB (4 k16-halves)
#define B_HI    16384                 // 16KB
#define B_LO    32768                 // 16KB
#define STAGE_B 49152
#define SMEM_BYTES (2 * STAGE_B)      // 98304

// Pre-converted A (fp16 rn), one-time pre-pass: 32MB scratch.
__device__ __half g_Ah[(size_t)T_TOK * D_IN];

__device__ __forceinline__ uint32_t swz(uint32_t a) {
    return a ^ ((a & 128u) >> 3);
}

__device__ __forceinline__ uint32_t smem_u32_of(const void* p) {
    uint32_t a;
    asm("{ .reg .u64 t; cvta.to.shared.u64 t, %1; cvt.u32.u64 %0, t; }" : "=r"(a) : "l"(p));
    return a;
}

__device__ __forceinline__ uint32_t pack2h(__half a, __half b) {
    __half2 t = __halves2half2(a, b);
    return *reinterpret_cast<uint32_t*>(&t);
}

__device__ __forceinline__ void sts8(uint32_t addr, uint32_t x, uint32_t y) {
    asm volatile("st.shared.v2.b32 [%0], {%1, %2};" :: "r"(addr), "r"(x), "r"(y) : "memory");
}

__device__ __forceinline__ void split_store_b4(float4 v, uint32_t hi_addr, uint32_t lo_addr) {
    __half h0 = __float2half_rn(v.x);
    __half h1 = __float2half_rn(v.y);
    __half h2 = __float2half_rn(v.z);
    __half h3 = __float2half_rn(v.w);
    __half l0 = __float2half_rn(v.x - __half2float(h0));
    __half l1 = __float2half_rn(v.y - __half2float(h1));
    __half l2 = __float2half_rn(v.z - __half2float(h2));
    __half l3 = __float2half_rn(v.w - __half2float(h3));
    sts8(hi_addr, pack2h(h0, h1), pack2h(h2, h3));
    sts8(lo_addr, pack2h(l0, l1), pack2h(l2, l3));
}

__device__ __forceinline__ void cp16(uint32_t dst, const void* src) {
    asm volatile("cp.async.cg.shared.global [%0], [%1], 16;"
                 :: "r"(dst), "l"(src) : "memory");
}
__device__ __forceinline__ void cp_commit() {
    asm volatile("cp.async.commit_group;" ::: "memory");
}
__device__ __forceinline__ void cp_wait0() {
    asm volatile("cp.async.wait_group 0;" ::: "memory");
}

__device__ __forceinline__ void ldsm_x4(uint32_t* r, uint32_t addr) {
    asm volatile("ldmatrix.sync.aligned.m8n8.x4.shared.b16 {%0,%1,%2,%3}, [%4];"
                 : "=r"(r[0]), "=r"(r[1]), "=r"(r[2]), "=r"(r[3]) : "r"(addr));
}

__device__ __forceinline__ void mma_f16(float* d, const uint32_t* a, uint32_t b0, uint32_t b1) {
    asm volatile(
        "mma.sync.aligned.m16n8k16.row.col.f32.f16.f16.f32 "
        "{%0,%1,%2,%3}, {%4,%5,%6,%7}, {%8,%9}, {%0,%1,%2,%3};"
        : "+f"(d[0]), "+f"(d[1]), "+f"(d[2]), "+f"(d[3])
        : "r"(a[0]), "r"(a[1]), "r"(a[2]), "r"(a[3]), "r"(b0), "r"(b1));
}

// ---- pre-pass: A fp32 -> fp16 (rn). 4 elems/thread. ----
__global__ __launch_bounds__(256)
void convert_A_kernel(const float* __restrict__ src) {
    size_t i = (size_t)blockIdx.x * 256 + threadIdx.x;   // float4 index
    float4 v = reinterpret_cast<const float4*>(src)[i];
    uint2 h = make_uint2(pack2h(__float2half_rn(v.x), __float2half_rn(v.y)),
                         pack2h(__float2half_rn(v.z), __float2half_rn(v.w)));
    reinterpret_cast<uint2*>(g_Ah)[i] = h;
}

__global__ __launch_bounds__(THREADS, 2)
void moe_gemm_f16c_kernel(const float* __restrict__ weight,  // [E, D_OUT, D_IN]
                          const float* __restrict__ bias,    // [E, D_OUT]
                          const int*   __restrict__ cnt,     // [E]
                          float*       __restrict__ out)     // [T, D_OUT]
{
    extern __shared__ char smem[];
    const uint32_t sbase = smem_u32_of(smem);

    const int tid = threadIdx.x;
    const int wid = tid >> 5;
    const int lid = tid & 31;

    const int nBase = blockIdx.x * BN;
    const int mBase = blockIdx.y * BM;

    int e = 0;
    {
        int acc = 0;
        #pragma unroll
        for (int i = 0; i < NUM_E; i++) {
            int c = cnt[i];
            if (mBase >= acc + c) { acc += c; e = i + 1; }
        }
    }
    const float* wptr = weight + (size_t)e * D_OUT * D_IN;

    const int warp_m = (wid >> 2) * 64;
    const int warp_n = (wid & 3) * 32;

    // ldmatrix lane addressing (verified rounds 3-11)
    const int a_row = (lid & 7) + ((lid >> 3) & 1) * 8;
    const int a_c2  = (lid >> 4) & 1;
    const int b_row = (lid & 7) + ((lid >> 4) & 1) * 8;
    const int b_c2  = (lid >> 3) & 1;

    // B staging (fp32 LDG + split + STS), round-11 mapping.
    const int srow = wid * 4 + (lid >> 3);
    const int quad = lid & 7;
    const uint32_t piece = swz((uint32_t)(srow * 32 + (quad & 3) * 8));
    const uint32_t h_lo = (uint32_t)((quad >> 2) * REG_SZ);
    const uint32_t h_hi = h_lo + 2 * REG_SZ;
    const float* bG = wptr + (size_t)(nBase + srow) * D_IN + quad * 4;

    // A cp.async mapping: 1024 x16B pieces per chunk (128 rows x 128B),
    // 4 per thread. idx = o*256+tid: row = idx>>3, p = idx&7;
    // dst half = p>>1, 16B slot q = p&1.
    const __half* aH = g_Ah + (size_t)mBase * D_IN;
    uint32_t a_dst[4];
    int a_row_o[4], a_p[4];
    #pragma unroll
    for (int o = 0; o < 4; o++) {
        int idx = o * 256 + tid;
        a_row_o[o] = idx >> 3;
        a_p[o]     = idx & 7;
        a_dst[o] = (uint32_t)((a_p[o] >> 1) * REG_SZ) +
                   swz((uint32_t)(a_row_o[o] * 32 + (a_p[o] & 1) * 16));
    }

    float d[4][4][4];
    #pragma unroll
    for (int f = 0; f < 4; f++)
        #pragma unroll
        for (int n = 0; n < 4; n++)
            #pragma unroll
            for (int k = 0; k < 4; k++)
                d[f][n][k] = 0.0f;

    auto issue_a = [&](int chunk, uint32_t st) {
        const int kb = chunk * BK;
        #pragma unroll
        for (int o = 0; o < 4; o++) {
            cp16(st + A_T + a_dst[o],
                 aH + (size_t)a_row_o[o] * D_IN + kb + a_p[o] * 8);
        }
    };

    auto k16 = [&](uint32_t hb) {
        uint32_t bh[2][4], bl[2][4];
        #pragma unroll
        for (int nb = 0; nb < 2; nb++) {
            uint32_t a = swz((uint32_t)((warp_n + nb * 16 + b_row) * 32 + b_c2 * 16));
            ldsm_x4(bh[nb], hb + B_HI + a);
            ldsm_x4(bl[nb], hb + B_LO + a);
        }
        uint32_t af[4][4];
        #pragma unroll
        for (int f = 0; f < 4; f++) {
            uint32_t a = swz((uint32_t)((warp_m + f * 16 + a_row) * 32 + a_c2 * 16));
            ldsm_x4(af[f], hb + A_T + a);
        }
        #pragma unroll
        for (int f = 0; f < 4; f++)
            #pragma unroll
            for (int nb = 0; nb < 2; nb++) {
                mma_f16(d[f][nb * 2 + 0], af[f], bh[nb][0], bh[nb][1]);
                mma_f16(d[f][nb * 2 + 1], af[f], bh[nb][2], bh[nb][3]);
            }
        #pragma unroll
        for (int f = 0; f < 4; f++)
            #pragma unroll
            for (int nb = 0; nb < 2; nb++) {
                mma_f16(d[f][nb * 2 + 0], af[f], bl[nb][0], bl[nb][1]);
                mma_f16(d[f][nb * 2 + 1], af[f], bl[nb][2], bl[nb][3]);
            }
    };

    // ---- prologue: chunk 0 into stage 0 ----
    issue_a(0, sbase);
    cp_commit();
    {
        #pragma unroll
        for (int sub = 0; sub < 2; sub++) {
            float4 s[4];
            #pragma unroll
            for (int r = 0; r < 4; r++)
                s[r] = *reinterpret_cast<const float4*>(bG + sub * 32 + (size_t)(r * 32) * D_IN);
            const uint32_t ho = (sub ? h_hi : h_lo);
            #pragma unroll
            for (int r = 0; r < 4; r++)
                split_store_b4(s[r], sbase + B_HI + ho + piece + (uint32_t)(r * 1024),
                                     sbase + B_LO + ho + piece + (uint32_t)(r * 1024));
        }
    }
    cp_wait0();
    __syncthreads();

    float4 s[4];

    #pragma unroll 1
    for (int i = 0; i < NCHUNK; i++) {
        const uint32_t cur = sbase + (uint32_t)(i & 1) * STAGE_B;
        const uint32_t nxt = sbase + (uint32_t)((i + 1) & 1) * STAGE_B;
        const bool pf = (i + 1 < NCHUNK);
        const int kb = (i + 1) * BK;

        // issue A(i+1) async; it completes by end of this chunk
        if (pf) { issue_a(i + 1, nxt); cp_commit(); }

        k16(cur);

        // slot: LDG B sub0
        if (pf) {
            #pragma unroll
            for (int r = 0; r < 4; r++)
                s[r] = *reinterpret_cast<const float4*>(bG + kb + (size_t)(r * 32) * D_IN);
        }
        k16(cur + REG_SZ);

        // slot: STS B sub0, LDG B sub1
        if (pf) {
            #pragma unroll
            for (int r = 0; r < 4; r++)
                split_store_b4(s[r], nxt + B_HI + h_lo + piece + (uint32_t)(r * 1024),
                                     nxt + B_LO + h_lo + piece + (uint32_t)(r * 1024));
            #pragma unroll
            for (int r = 0; r < 4; r++)
                s[r] = *reinterpret_cast<const float4*>(bG + kb + 32 + (size_t)(r * 32) * D_IN);
        }
        k16(cur + 2 * REG_SZ);

        // slot: STS B sub1
        if (pf) {
            #pragma unroll
            for (int r = 0; r < 4; r++)
                split_store_b4(s[r], nxt + B_HI + h_hi + piece + (uint32_t)(r * 1024),
                                     nxt + B_LO + h_hi + piece + (uint32_t)(r * 1024));
        }
        k16(cur + 3 * REG_SZ);

        cp_wait0();
        __syncthreads();
    }

    // ---- epilogue: bias + fp32 store ----
    const int g  = lid >> 2;
    const int t4 = lid & 3;
    const float* brow = bias + (size_t)e * D_OUT;
    #pragma unroll
    for (int f = 0; f < 4; f++) {
        const int row0 = mBase + warp_m + f * 16 + g;
        #pragma unroll
        for (int nf = 0; nf < 4; nf++) {
            const int col = nBase + warp_n + nf * 8 + t4 * 2;
            float2 bv = *reinterpret_cast<const float2*>(brow + col);
            float2 o0, o1;
            o0.x = d[f][nf][0] + bv.x;
            o0.y = d[f][nf][1] + bv.y;
            o1.x = d[f][nf][2] + bv.x;
            o1.y = d[f][nf][3] + bv.y;
            *reinterpret_cast<float2*>(out + (size_t)row0 * D_OUT + col) = o0;
            *reinterpret_cast<float2*>(out + (size_t)(row0 + 8) * D_OUT + col) = o1;
        }
    }
}

extern "C" void kernel_launch(void* const* d_in, const int* in_sizes, int n_in,
                              void* d_out, int out_size)
{
    const float* inp    = (const float*)d_in[0];
    const float* weight = (const float*)d_in[1];
    const float* bias   = (const float*)d_in[2];
    const int*   cnt    = (const int*)d_in[3];
    float* out = (float*)d_out;

    // one-time A convert: 4.19M float4 -> 16384 blocks x 256
    convert_A_kernel<<<(unsigned)((size_t)T_TOK * D_IN / 4 / 256), 256>>>(inp);

    cudaFuncSetAttribute(moe_gemm_f16c_kernel,
                         cudaFuncAttributeMaxDynamicSharedMemorySize, SMEM_BYTES);

    dim3 grid(D_OUT / BN, T_TOK / BM);   // (64, 64)
    moe_gemm_f16c_kernel<<<grid, THREADS, SMEM_BYTES>>>(weight, bias, cnt, out);
}

// round 13
// speedup vs baseline: 1.0329x; 1.0329x over previous
#include <cuda_runtime.h>
#include <cuda_fp16.h>
#include <cstdint>

#define NUM_E 16
#define D_IN  2048
#define D_OUT 8192
#define T_TOK 8192

// CTA 128(M) x 128(N), BK=64 (4 k16 steps/chunk). 8 warps = 2(M) x 4(N),
// warp tile 64x32. fp16 2-term (A rn via pre-pass + cp.async, B hi+lo in-kernel).
#define BM 128
#define BN 128
#define BK 64
#define NCHUNK (D_IN / BK)   // 32
#define THREADS 256

#define REG_SZ  4096
#define A_T     0                     // 16KB (4 k16-halves)
#define B_HI    16384                 // 16KB
#define B_LO    32768                 // 16KB
#define STAGE_B 49152
#define SMEM_BYTES (2 * STAGE_B)      // 98304

// Pre-converted A (fp16 rn), one-time pre-pass: 32MB scratch.
__device__ __half g_Ah[(size_t)T_TOK * D_IN];

__device__ __forceinline__ uint32_t swz(uint32_t a) {
    return a ^ ((a & 128u) >> 3);
}

__device__ __forceinline__ uint32_t smem_u32_of(const void* p) {
    uint32_t a;
    asm("{ .reg .u64 t; cvta.to.shared.u64 t, %1; cvt.u32.u64 %0, t; }" : "=r"(a) : "l"(p));
    return a;
}

__device__ __forceinline__ uint32_t pack2h(__half a, __half b) {
    __half2 t = __halves2half2(a, b);
    return *reinterpret_cast<uint32_t*>(&t);
}

__device__ __forceinline__ void sts8(uint32_t addr, uint32_t x, uint32_t y) {
    asm volatile("st.shared.v2.b32 [%0], {%1, %2};" :: "r"(addr), "r"(x), "r"(y) : "memory");
}

__device__ __forceinline__ void split_store_b4(float4 v, uint32_t hi_addr, uint32_t lo_addr) {
    __half h0 = __float2half_rn(v.x);
    __half h1 = __float2half_rn(v.y);
    __half h2 = __float2half_rn(v.z);
    __half h3 = __float2half_rn(v.w);
    __half l0 = __float2half_rn(v.x - __half2float(h0));
    __half l1 = __float2half_rn(v.y - __half2float(h1));
    __half l2 = __float2half_rn(v.z - __half2float(h2));
    __half l3 = __float2half_rn(v.w - __half2float(h3));
    sts8(hi_addr, pack2h(h0, h1), pack2h(h2, h3));
    sts8(lo_addr, pack2h(l0, l1), pack2h(l2, l3));
}

__device__ __forceinline__ void cp16(uint32_t dst, const void* src) {
    asm volatile("cp.async.cg.shared.global [%0], [%1], 16;"
                 :: "r"(dst), "l"(src) : "memory");
}
__device__ __forceinline__ void cp_commit() {
    asm volatile("cp.async.commit_group;" ::: "memory");
}
__device__ __forceinline__ void cp_wait0() {
    asm volatile("cp.async.wait_group 0;" ::: "memory");
}

__device__ __forceinline__ void ldsm_x4(uint32_t* r, uint32_t addr) {
    asm volatile("ldmatrix.sync.aligned.m8n8.x4.shared.b16 {%0,%1,%2,%3}, [%4];"
                 : "=r"(r[0]), "=r"(r[1]), "=r"(r[2]), "=r"(r[3]) : "r"(addr));
}

__device__ __forceinline__ void mma_f16(float* d, const uint32_t* a, uint32_t b0, uint32_t b1) {
    asm volatile(
        "mma.sync.aligned.m16n8k16.row.col.f32.f16.f16.f32 "
        "{%0,%1,%2,%3}, {%4,%5,%6,%7}, {%8,%9}, {%0,%1,%2,%3};"
        : "+f"(d[0]), "+f"(d[1]), "+f"(d[2]), "+f"(d[3])
        : "r"(a[0]), "r"(a[1]), "r"(a[2]), "r"(a[3]), "r"(b0), "r"(b1));
}

// ---- pre-pass: A fp32 -> fp16 (rn). 4 elems/thread. ----
__global__ __launch_bounds__(256)
void convert_A_kernel(const float* __restrict__ src) {
    size_t i = (size_t)blockIdx.x * 256 + threadIdx.x;   // float4 index
    float4 v = reinterpret_cast<const float4*>(src)[i];
    uint2 h = make_uint2(pack2h(__float2half_rn(v.x), __float2half_rn(v.y)),
                         pack2h(__float2half_rn(v.z), __float2half_rn(v.w)));
    reinterpret_cast<uint2*>(g_Ah)[i] = h;
}

__global__ __launch_bounds__(THREADS, 2)
void moe_gemm_f16d_kernel(const float* __restrict__ weight,  // [E, D_OUT, D_IN]
                          const float* __restrict__ bias,    // [E, D_OUT]
                          const int*   __restrict__ cnt,     // [E]
                          float*       __restrict__ out)     // [T, D_OUT]
{
    extern __shared__ char smem[];
    const uint32_t sbase = smem_u32_of(smem);

    const int tid = threadIdx.x;
    const int wid = tid >> 5;
    const int lid = tid & 31;

    const int nBase = blockIdx.x * BN;
    const int mBase = blockIdx.y * BM;

    int e = 0;
    {
        int acc = 0;
        #pragma unroll
        for (int i = 0; i < NUM_E; i++) {
            int c = cnt[i];
            if (mBase >= acc + c) { acc += c; e = i + 1; }
        }
    }
    const float* wptr = weight + (size_t)e * D_OUT * D_IN;

    const int warp_m = (wid >> 2) * 64;
    const int warp_n = (wid & 3) * 32;

    // ldmatrix lane addressing (verified rounds 3-12)
    const int a_row = (lid & 7) + ((lid >> 3) & 1) * 8;
    const int a_c2  = (lid >> 4) & 1;
    const int b_row = (lid & 7) + ((lid >> 4) & 1) * 8;
    const int b_c2  = (lid >> 3) & 1;

    // B staging (fp32 LDG + split + STS)
    const int srow = wid * 4 + (lid >> 3);
    const int quad = lid & 7;
    const uint32_t piece = swz((uint32_t)(srow * 32 + (quad & 3) * 8));
    const uint32_t h_lo = (uint32_t)((quad >> 2) * REG_SZ);
    const uint32_t h_hi = h_lo + 2 * REG_SZ;
    const float* bG = wptr + (size_t)(nBase + srow) * D_IN + quad * 4;

    // A cp.async mapping: 1024 x16B pieces per chunk, 4 per thread.
    const __half* aH = g_Ah + (size_t)mBase * D_IN;
    uint32_t a_dst[4];
    int a_row_o[4], a_p[4];
    #pragma unroll
    for (int o = 0; o < 4; o++) {
        int idx = o * 256 + tid;
        a_row_o[o] = idx >> 3;
        a_p[o]     = idx & 7;
        a_dst[o] = (uint32_t)((a_p[o] >> 1) * REG_SZ) +
                   swz((uint32_t)(a_row_o[o] * 32 + (a_p[o] & 1) * 16));
    }

    float d[4][4][4];
    #pragma unroll
    for (int f = 0; f < 4; f++)
        #pragma unroll
        for (int n = 0; n < 4; n++)
            #pragma unroll
            for (int k = 0; k < 4; k++)
                d[f][n][k] = 0.0f;

    auto issue_a = [&](int chunk, uint32_t st) {
        const int kb = chunk * BK;
        #pragma unroll
        for (int o = 0; o < 4; o++) {
            cp16(st + A_T + a_dst[o],
                 aH + (size_t)a_row_o[o] * D_IN + kb + a_p[o] * 8);
        }
    };

    auto k16 = [&](uint32_t hb) {
        uint32_t bh[2][4], bl[2][4];
        #pragma unroll
        for (int nb = 0; nb < 2; nb++) {
            uint32_t a = swz((uint32_t)((warp_n + nb * 16 + b_row) * 32 + b_c2 * 16));
            ldsm_x4(bh[nb], hb + B_HI + a);
            ldsm_x4(bl[nb], hb + B_LO + a);
        }
        uint32_t af[4][4];
        #pragma unroll
        for (int f = 0; f < 4; f++) {
            uint32_t a = swz((uint32_t)((warp_m + f * 16 + a_row) * 32 + a_c2 * 16));
            ldsm_x4(af[f], hb + A_T + a);
        }
        #pragma unroll
        for (int f = 0; f < 4; f++)
            #pragma unroll
            for (int nb = 0; nb < 2; nb++) {
                mma_f16(d[f][nb * 2 + 0], af[f], bh[nb][0], bh[nb][1]);
                mma_f16(d[f][nb * 2 + 1], af[f], bh[nb][2], bh[nb][3]);
            }
        #pragma unroll
        for (int f = 0; f < 4; f++)
            #pragma unroll
            for (int nb = 0; nb < 2; nb++) {
                mma_f16(d[f][nb * 2 + 0], af[f], bl[nb][0], bl[nb][1]);
                mma_f16(d[f][nb * 2 + 1], af[f], bl[nb][2], bl[nb][3]);
            }
    };

    // ---- prologue: chunk 0 into stage 0 ----
    issue_a(0, sbase);
    cp_commit();
    {
        #pragma unroll
        for (int sub = 0; sub < 2; sub++) {
            float4 s[4];
            #pragma unroll
            for (int r = 0; r < 4; r++)
                s[r] = *reinterpret_cast<const float4*>(bG + sub * 32 + (size_t)(r * 32) * D_IN);
            const uint32_t ho = (sub ? h_hi : h_lo);
            #pragma unroll
            for (int r = 0; r < 4; r++)
                split_store_b4(s[r], sbase + B_HI + ho + piece + (uint32_t)(r * 1024),
                                     sbase + B_LO + ho + piece + (uint32_t)(r * 1024));
        }
    }
    cp_wait0();
    __syncthreads();

    float4 s[4];

    #pragma unroll 1
    for (int i = 0; i < NCHUNK; i++) {
        const uint32_t cur = sbase + (uint32_t)(i & 1) * STAGE_B;
        const uint32_t nxt = sbase + (uint32_t)((i + 1) & 1) * STAGE_B;
        const bool pf = (i + 1 < NCHUNK);
        const int kb = (i + 1) * BK;

        // slot 0: A(i+1) cp.async + LDG B sub0 (early — a full k16 before STS)
        if (pf) {
            issue_a(i + 1, nxt);
            cp_commit();
            #pragma unroll
            for (int r = 0; r < 4; r++)
                s[r] = *reinterpret_cast<const float4*>(bG + kb + (size_t)(r * 32) * D_IN);
        }
        k16(cur);

        // slot 1: STS B sub0, LDG B sub1
        if (pf) {
            #pragma unroll
            for (int r = 0; r < 4; r++)
                split_store_b4(s[r], nxt + B_HI + h_lo + piece + (uint32_t)(r * 1024),
                                     nxt + B_LO + h_lo + piece + (uint32_t)(r * 1024));
            #pragma unroll
            for (int r = 0; r < 4; r++)
                s[r] = *reinterpret_cast<const float4*>(bG + kb + 32 + (size_t)(r * 32) * D_IN);
        }
        k16(cur + REG_SZ);

        // slot 2: STS B sub1
        if (pf) {
            #pragma unroll
            for (int r = 0; r < 4; r++)
                split_store_b4(s[r], nxt + B_HI + h_hi + piece + (uint32_t)(r * 1024),
                                     nxt + B_LO + h_hi + piece + (uint32_t)(r * 1024));
        }
        k16(cur + 2 * REG_SZ);

        // slot 3: pure compute
        k16(cur + 3 * REG_SZ);

        cp_wait0();
        __syncthreads();
    }

    // ---- epilogue: bias + fp32 store ----
    const int g  = lid >> 2;
    const int t4 = lid & 3;
    const float* brow = bias + (size_t)e * D_OUT;
    #pragma unroll
    for (int f = 0; f < 4; f++) {
        const int row0 = mBase + warp_m + f * 16 + g;
        #pragma unroll
        for (int nf = 0; nf < 4; nf++) {
            const int col = nBase + warp_n + nf * 8 + t4 * 2;
            float2 bv = *reinterpret_cast<const float2*>(brow + col);
            float2 o0, o1;
            o0.x = d[f][nf][0] + bv.x;
            o0.y = d[f][nf][1] + bv.y;
            o1.x = d[f][nf][2] + bv.x;
            o1.y = d[f][nf][3] + bv.y;
            *reinterpret_cast<float2*>(out + (size_t)row0 * D_OUT + col) = o0;
            *reinterpret_cast<float2*>(out + (size_t)(row0 + 8) * D_OUT + col) = o1;
        }
    }
}

extern "C" void kernel_launch(void* const* d_in, const int* in_sizes, int n_in,
                              void* d_out, int out_size)
{
    const float* inp    = (const float*)d_in[0];
    const float* weight = (const float*)d_in[1];
    const float* bias   = (const float*)d_in[2];
    const int*   cnt    = (const int*)d_in[3];
    float* out = (float*)d_out;

    convert_A_kernel<<<(unsigned)((size_t)T_TOK * D_IN / 4 / 256), 256>>>(inp);

    cudaFuncSetAttribute(moe_gemm_f16d_kernel,
                         cudaFuncAttributeMaxDynamicSharedMemorySize, SMEM_BYTES);

    dim3 grid(D_OUT / BN, T_TOK / BM);   // (64, 64)
    moe_gemm_f16d_kernel<<<grid, THREADS, SMEM_BYTES>>>(weight, bias, cnt, out);
}

// round 14
// speedup vs baseline: 1.4069x; 1.3621x over previous
#include <cuda_runtime.h>
#include <cuda_fp16.h>
#include <cstdint>

#define NUM_E 16
#define D_IN  2048
#define D_OUT 8192
#define T_TOK 8192

// CTA 128(M) x 128(N), BK=64 (4 k16 steps/chunk). 8 warps = 2(M) x 4(N),
// warp tile 64x32. Single-term fp16 (A and B both rn-rounded; quadrature
// error ~2.9e-4 < 1e-3, model validated rounds 3-13).
#define BM 128
#define BN 128
#define BK 64
#define NCHUNK (D_IN / BK)   // 32
#define THREADS 256

#define REG_SZ  4096
#define A_T     0                     // 16KB (4 k16-halves)
#define B_T     16384                 // 16KB
#define STAGE_B 32768
#define SMEM_BYTES (2 * STAGE_B)      // 65536

// Pre-converted A (fp16 rn), one-time pre-pass: 32MB scratch.
__device__ __half g_Ah[(size_t)T_TOK * D_IN];

__device__ __forceinline__ uint32_t swz(uint32_t a) {
    return a ^ ((a & 128u) >> 3);
}

__device__ __forceinline__ uint32_t smem_u32_of(const void* p) {
    uint32_t a;
    asm("{ .reg .u64 t; cvta.to.shared.u64 t, %1; cvt.u32.u64 %0, t; }" : "=r"(a) : "l"(p));
    return a;
}

__device__ __forceinline__ uint32_t pack2h(__half a, __half b) {
    __half2 t = __halves2half2(a, b);
    return *reinterpret_cast<uint32_t*>(&t);
}

__device__ __forceinline__ void sts8(uint32_t addr, uint32_t x, uint32_t y) {
    asm volatile("st.shared.v2.b32 [%0], {%1, %2};" :: "r"(addr), "r"(x), "r"(y) : "memory");
}

// rn-round a float4 to fp16 and store 8B.
__device__ __forceinline__ void store_h4(float4 v, uint32_t addr) {
    sts8(addr,
         pack2h(__float2half_rn(v.x), __float2half_rn(v.y)),
         pack2h(__float2half_rn(v.z), __float2half_rn(v.w)));
}

__device__ __forceinline__ void cp16(uint32_t dst, const void* src) {
    asm volatile("cp.async.cg.shared.global [%0], [%1], 16;"
                 :: "r"(dst), "l"(src) : "memory");
}
__device__ __forceinline__ void cp_commit() {
    asm volatile("cp.async.commit_group;" ::: "memory");
}
__device__ __forceinline__ void cp_wait0() {
    asm volatile("cp.async.wait_group 0;" ::: "memory");
}

__device__ __forceinline__ void ldsm_x4(uint32_t* r, uint32_t addr) {
    asm volatile("ldmatrix.sync.aligned.m8n8.x4.shared.b16 {%0,%1,%2,%3}, [%4];"
                 : "=r"(r[0]), "=r"(r[1]), "=r"(r[2]), "=r"(r[3]) : "r"(addr));
}

__device__ __forceinline__ void mma_f16(float* d, const uint32_t* a, uint32_t b0, uint32_t b1) {
    asm volatile(
        "mma.sync.aligned.m16n8k16.row.col.f32.f16.f16.f32 "
        "{%0,%1,%2,%3}, {%4,%5,%6,%7}, {%8,%9}, {%0,%1,%2,%3};"
        : "+f"(d[0]), "+f"(d[1]), "+f"(d[2]), "+f"(d[3])
        : "r"(a[0]), "r"(a[1]), "r"(a[2]), "r"(a[3]), "r"(b0), "r"(b1));
}

// ---- pre-pass: A fp32 -> fp16 (rn). 4 elems/thread. ----
__global__ __launch_bounds__(256)
void convert_A_kernel(const float* __restrict__ src) {
    size_t i = (size_t)blockIdx.x * 256 + threadIdx.x;
    float4 v = reinterpret_cast<const float4*>(src)[i];
    uint2 h = make_uint2(pack2h(__float2half_rn(v.x), __float2half_rn(v.y)),
                         pack2h(__float2half_rn(v.z), __float2half_rn(v.w)));
    reinterpret_cast<uint2*>(g_Ah)[i] = h;
}

__global__ __launch_bounds__(THREADS, 2)
void moe_gemm_f16e_kernel(const float* __restrict__ weight,  // [E, D_OUT, D_IN]
                          const float* __restrict__ bias,    // [E, D_OUT]
                          const int*   __restrict__ cnt,     // [E]
                          float*       __restrict__ out)     // [T, D_OUT]
{
    extern __shared__ char smem[];
    const uint32_t sbase = smem_u32_of(smem);

    const int tid = threadIdx.x;
    const int wid = tid >> 5;
    const int lid = tid & 31;

    const int nBase = blockIdx.x * BN;
    const int mBase = blockIdx.y * BM;

    int e = 0;
    {
        int acc = 0;
        #pragma unroll
        for (int i = 0; i < NUM_E; i++) {
            int c = cnt[i];
            if (mBase >= acc + c) { acc += c; e = i + 1; }
        }
    }
    const float* wptr = weight + (size_t)e * D_OUT * D_IN;

    const int warp_m = (wid >> 2) * 64;
    const int warp_n = (wid & 3) * 32;

    // ldmatrix lane addressing (verified rounds 3-13)
    const int a_row = (lid & 7) + ((lid >> 3) & 1) * 8;
    const int a_c2  = (lid >> 4) & 1;
    const int b_row = (lid & 7) + ((lid >> 4) & 1) * 8;
    const int b_c2  = (lid >> 3) & 1;

    // B staging (fp32 LDG + rn convert + STS), round-11 mapping.
    const int srow = wid * 4 + (lid >> 3);
    const int quad = lid & 7;
    const uint32_t piece = swz((uint32_t)(srow * 32 + (quad & 3) * 8));
    const uint32_t h_lo = (uint32_t)((quad >> 2) * REG_SZ);
    const uint32_t h_hi = h_lo + 2 * REG_SZ;
    const float* bG = wptr + (size_t)(nBase + srow) * D_IN + quad * 4;

    // A cp.async mapping: 1024 x16B pieces per chunk, 4 per thread.
    const __half* aH = g_Ah + (size_t)mBase * D_IN;
    uint32_t a_dst[4];
    int a_row_o[4], a_p[4];
    #pragma unroll
    for (int o = 0; o < 4; o++) {
        int idx = o * 256 + tid;
        a_row_o[o] = idx >> 3;
        a_p[o]     = idx & 7;
        a_dst[o] = (uint32_t)((a_p[o] >> 1) * REG_SZ) +
                   swz((uint32_t)(a_row_o[o] * 32 + (a_p[o] & 1) * 16));
    }

    float d[4][4][4];
    #pragma unroll
    for (int f = 0; f < 4; f++)
        #pragma unroll
        for (int n = 0; n < 4; n++)
            #pragma unroll
            for (int k = 0; k < 4; k++)
                d[f][n][k] = 0.0f;

    auto issue_a = [&](int chunk, uint32_t st) {
        const int kb = chunk * BK;
        #pragma unroll
        for (int o = 0; o < 4; o++) {
            cp16(st + A_T + a_dst[o],
                 aH + (size_t)a_row_o[o] * D_IN + kb + a_p[o] * 8);
        }
    };

    auto k16 = [&](uint32_t hb) {
        uint32_t bh[2][4];
        #pragma unroll
        for (int nb = 0; nb < 2; nb++) {
            uint32_t a = swz((uint32_t)((warp_n + nb * 16 + b_row) * 32 + b_c2 * 16));
            ldsm_x4(bh[nb], hb + B_T + a);
        }
        uint32_t af[4][4];
        #pragma unroll
        for (int f = 0; f < 4; f++) {
            uint32_t a = swz((uint32_t)((warp_m + f * 16 + a_row) * 32 + a_c2 * 16));
            ldsm_x4(af[f], hb + A_T + a);
        }
        #pragma unroll
        for (int f = 0; f < 4; f++)
            #pragma unroll
            for (int nb = 0; nb < 2; nb++) {
                mma_f16(d[f][nb * 2 + 0], af[f], bh[nb][0], bh[nb][1]);
                mma_f16(d[f][nb * 2 + 1], af[f], bh[nb][2], bh[nb][3]);
            }
    };

    // ---- prologue: chunk 0 into stage 0 ----
    issue_a(0, sbase);
    cp_commit();
    {
        #pragma unroll
        for (int sub = 0; sub < 2; sub++) {
            float4 s[4];
            #pragma unroll
            for (int r = 0; r < 4; r++)
                s[r] = *reinterpret_cast<const float4*>(bG + sub * 32 + (size_t)(r * 32) * D_IN);
            const uint32_t ho = (sub ? h_hi : h_lo);
            #pragma unroll
            for (int r = 0; r < 4; r++)
                store_h4(s[r], sbase + B_T + ho + piece + (uint32_t)(r * 1024));
        }
    }
    cp_wait0();
    __syncthreads();

    float4 s[4];

    #pragma unroll 1
    for (int i = 0; i < NCHUNK; i++) {
        const uint32_t cur = sbase + (uint32_t)(i & 1) * STAGE_B;
        const uint32_t nxt = sbase + (uint32_t)((i + 1) & 1) * STAGE_B;
        const bool pf = (i + 1 < NCHUNK);
        const int kb = (i + 1) * BK;

        // slot 0: A(i+1) cp.async + LDG B sub0
        if (pf) {
            issue_a(i + 1, nxt);
            cp_commit();
            #pragma unroll
            for (int r = 0; r < 4; r++)
                s[r] = *reinterpret_cast<const float4*>(bG + kb + (size_t)(r * 32) * D_IN);
        }
        k16(cur);

        // slot 1: STS B sub0, LDG B sub1
        if (pf) {
            #pragma unroll
            for (int r = 0; r < 4; r++)
                store_h4(s[r], nxt + B_T + h_lo + piece + (uint32_t)(r * 1024));
            #pragma unroll
            for (int r = 0; r < 4; r++)
                s[r] = *reinterpret_cast<const float4*>(bG + kb + 32 + (size_t)(r * 32) * D_IN);
        }
        k16(cur + REG_SZ);

        // slot 2: STS B sub1
        if (pf) {
            #pragma unroll
            for (int r = 0; r < 4; r++)
                store_h4(s[r], nxt + B_T + h_hi + piece + (uint32_t)(r * 1024));
        }
        k16(cur + 2 * REG_SZ);

        // slot 3: pure compute
        k16(cur + 3 * REG_SZ);

        cp_wait0();
        __syncthreads();
    }

    // ---- epilogue: bias + fp32 store ----
    const int g  = lid >> 2;
    const int t4 = lid & 3;
    const float* brow = bias + (size_t)e * D_OUT;
    #pragma unroll
    for (int f = 0; f < 4; f++) {
        const int row0 = mBase + warp_m + f * 16 + g;
        #pragma unroll
        for (int nf = 0; nf < 4; nf++) {
            const int col = nBase + warp_n + nf * 8 + t4 * 2;
            float2 bv = *reinterpret_cast<const float2*>(brow + col);
            float2 o0, o1;
            o0.x = d[f][nf][0] + bv.x;
            o0.y = d[f][nf][1] + bv.y;
            o1.x = d[f][nf][2] + bv.x;
            o1.y = d[f][nf][3] + bv.y;
            *reinterpret_cast<float2*>(out + (size_t)row0 * D_OUT + col) = o0;
            *reinterpret_cast<float2*>(out + (size_t)(row0 + 8) * D_OUT + col) = o1;
        }
    }
}

extern "C" void kernel_launch(void* const* d_in, const int* in_sizes, int n_in,
                              void* d_out, int out_size)
{
    const float* inp    = (const float*)d_in[0];
    const float* weight = (const float*)d_in[1];
    const float* bias   = (const float*)d_in[2];
    const int*   cnt    = (const int*)d_in[3];
    float* out = (float*)d_out;

    convert_A_kernel<<<(unsigned)((size_t)T_TOK * D_IN / 4 / 256), 256>>>(inp);

    cudaFuncSetAttribute(moe_gemm_f16e_kernel,
                         cudaFuncAttributeMaxDynamicSharedMemorySize, SMEM_BYTES);

    dim3 grid(D_OUT / BN, T_TOK / BM);   // (64, 64)
    moe_gemm_f16e_kernel<<<grid, THREADS, SMEM_BYTES>>>(weight, bias, cnt, out);
}